// round 12
// baseline (speedup 1.0000x reference)
#include <cuda_runtime.h>
#include <cuda_bf16.h>

// Problem constants (match reference)
#define B_SZ       128
#define S_SZ       4096
#define TOK        64          // token_dim
#define EFF        60          // token_dim - 4
#define NF         20          // num features
#define H0         256
#define H1         128
#define H2         64
#define OUT        3
#define CHUNKS     4
#define CHUNK_S    (S_SZ / CHUNKS)   // 1024 tokens per chunk
#define BPB        8                 // batches per MLP block
#define MLP_BLOCKS (B_SZ / BPB)      // 16
#define NT_MLP     512

// Scratch: partial column sums per (batch, chunk): [B, CHUNKS, TOK]
__device__ float g_partial[B_SZ * CHUNKS * TOK];

__device__ __forceinline__ void l2_prefetch(const void* p) {
    asm volatile("prefetch.global.L2 [%0];" :: "l"(p));
}

// ---------------------------------------------------------------------------
// Kernel 1: streaming column-sum (512 blocks x 256 threads — measured
// ~6.8 TB/s). Weight prefetch happens AFTER the streaming loop so the lines
// survive the L2 flush caused by the 134 MB stream.
// ---------------------------------------------------------------------------
__global__ __launch_bounds__(256, 8)
void mean_sum_kernel(const float* __restrict__ x,
                     const float* __restrict__ w_ext,
                     const float* __restrict__ w0,
                     const float* __restrict__ w1,
                     const float* __restrict__ w2) {
    const int b = blockIdx.x >> 2;        // batch
    const int c = blockIdx.x & 3;         // chunk
    const int t = threadIdx.x;            // 0..255
    const int blk = blockIdx.x;           // 0..511

    const float4* __restrict__ p =
        (const float4*)(x + ((size_t)b * S_SZ + (size_t)c * CHUNK_S) * TOK);

    // 16384 float4 per block; 64 per thread.
    float4 acc = make_float4(0.f, 0.f, 0.f, 0.f);
    #pragma unroll 16
    for (int i = t; i < CHUNK_S * (TOK / 4); i += 256) {
        float4 v = __ldcs(&p[i]);         // streaming: x touched once
        acc.x += v.x; acc.y += v.y; acc.z += v.z; acc.w += v.w;
    }

    // Post-stream L2 prefetch of MLP weights (disjoint slices, survives).
    if (t == 0)       l2_prefetch(w1 + (blk * 2 + 0) * 32);
    else if (t == 1)  l2_prefetch(w1 + (blk * 2 + 1) * 32);
    else if (t == 2 && blk < 256) l2_prefetch(w2 + blk * 32);
    else if (t == 3 && blk < 160) l2_prefetch(w0 + blk * 32);
    else if (t == 4 && blk < 38)  l2_prefetch(w_ext + blk * 32);

    __shared__ float4 sm[256];
    sm[t] = acc;
    __syncthreads();

    if (t < 16) {
        float4 s = make_float4(0.f, 0.f, 0.f, 0.f);
        #pragma unroll
        for (int k = 0; k < 16; k++) {
            float4 v = sm[t + k * 16];
            s.x += v.x; s.y += v.y; s.z += v.z; s.w += v.w;
        }
        float* dst = &g_partial[(size_t)(b * CHUNKS + c) * TOK + t * 4];
        dst[0] = s.x; dst[1] = s.y; dst[2] = s.z; dst[3] = s.w;
    }
}

// ---------------------------------------------------------------------------
// Kernel 2: MLP, 8 batches per block (16 blocks x 512 threads).
// Weight rows are loaded once per block and reused across 8 batches, cutting
// L2 weight traffic 8x (24 MB -> 3 MB) and pipelining 8 independent
// per-batch dependency chains inside every layer stage.
// ---------------------------------------------------------------------------
__global__ __launch_bounds__(NT_MLP, 1)
void mlp_kernel(const float* __restrict__ w_ext, const float* __restrict__ b_ext,
                const float* __restrict__ w0, const float* __restrict__ b0,
                const float* __restrict__ w1, const float* __restrict__ b1,
                const float* __restrict__ w2, const float* __restrict__ b2,
                const float* __restrict__ w3, const float* __restrict__ b3,
                float* __restrict__ out) {
    const int t = threadIdx.x;            // 0..511
    const int w = t >> 5;                 // warp 0..15
    const int lane = t & 31;
    const int base_b = blockIdx.x * BPB;  // first batch of this block

    __shared__ float xm[BPB][TOK];        // 2 KB
    __shared__ float feats[BPB][NF + 4];  // padded rows
    __shared__ float a0[BPB][H0];         // 8 KB
    __shared__ float a1[BPB][H1];         // 4 KB
    __shared__ float a2[BPB][H2];         // 2 KB

    // ---- Combine chunk partials -> means for 8 batches (512 values) -------
    {
        const int bb = t >> 6;            // 0..7
        const int col = t & 63;
        const float* p0 = &g_partial[(size_t)((base_b + bb) * CHUNKS) * TOK + col];
        float s = (p0[0] + p0[TOK]) + (p0[2 * TOK] + p0[3 * TOK]);
        xm[bb][col] = s * (1.0f / (float)S_SZ);
    }
    __syncthreads();

    // ---- Extractor: 20 neurons x 8 batches = 160 tasks, thread-per-task ---
    if (t < NF * BPB) {
        const int bb = t / NF;
        const int j = t - bb * NF;
        const float* __restrict__ wp = w_ext + j * EFF;   // tiny, L1-resident
        const float* xv = xm[bb];
        float s0 = b_ext[j], s1 = 0.f, s2 = 0.f, s3 = 0.f;
        #pragma unroll
        for (int k = 0; k < EFF; k += 4) {
            s0 = fmaf(xv[k + 0], wp[k + 0], s0);
            s1 = fmaf(xv[k + 1], wp[k + 1], s1);
            s2 = fmaf(xv[k + 2], wp[k + 2], s2);
            s3 = fmaf(xv[k + 3], wp[k + 3], s3);
        }
        feats[bb][j] = (s0 + s1) + (s2 + s3);
    }
    __syncthreads();

    // ---- Layer 0: 20 -> 256 + ReLU. 2048 tasks; thread does 1 neuron x 4
    //      batches, weight row loaded once and reused. -----------------------
    {
        const int n = t & 255;            // neuron
        const int bg = (t >> 8) * 4;      // batch group start: 0 or 4
        const float* __restrict__ wp = w0 + n * NF;
        float wreg[NF];
        #pragma unroll
        for (int k = 0; k < NF; k++) wreg[k] = wp[k];
        const float bias = b0[n];
        #pragma unroll
        for (int g = 0; g < 4; g++) {
            const int bb = bg + g;
            float s0 = bias, s1 = 0.f;
            #pragma unroll
            for (int k = 0; k < NF; k += 2) {
                s0 = fmaf(feats[bb][k + 0], wreg[k + 0], s0);
                s1 = fmaf(feats[bb][k + 1], wreg[k + 1], s1);
            }
            a0[bb][n] = fmaxf(s0 + s1, 0.f);
        }
    }
    __syncthreads();

    // ---- Layer 1: 256 -> 128 + ReLU. Warp-per-neuron (8 rounds), weight
    //      row loaded once (coalesced 1 KB), reused across 8 batches. --------
    {
        #pragma unroll
        for (int r = 0; r < 8; r++) {
            const int j = w + r * 16;
            const float4* __restrict__ wr = (const float4*)(w1 + j * H0);
            const float4 w0v = wr[lane];
            const float4 w1v = wr[lane + 32];
            const float bias = b1[j];
            #pragma unroll
            for (int bb = 0; bb < BPB; bb++) {
                const float4* ar = (const float4*)a0[bb];
                float4 a0v = ar[lane];
                float4 a1v = ar[lane + 32];
                float s0 = fmaf(a0v.x, w0v.x, a0v.y * w0v.y);
                float s1 = fmaf(a0v.z, w0v.z, a0v.w * w0v.w);
                float s2 = fmaf(a1v.x, w1v.x, a1v.y * w1v.y);
                float s3 = fmaf(a1v.z, w1v.z, a1v.w * w1v.w);
                float s = (s0 + s1) + (s2 + s3);
                s += __shfl_xor_sync(0xFFFFFFFF, s, 1);
                s += __shfl_xor_sync(0xFFFFFFFF, s, 2);
                s += __shfl_xor_sync(0xFFFFFFFF, s, 4);
                s += __shfl_xor_sync(0xFFFFFFFF, s, 8);
                s += __shfl_xor_sync(0xFFFFFFFF, s, 16);
                if (lane == 0) a1[bb][j] = fmaxf(s + bias, 0.f);
            }
        }
    }
    __syncthreads();

    // ---- Layer 2: 128 -> 64 + ReLU. Warp-per-neuron (4 rounds). -----------
    {
        #pragma unroll
        for (int r = 0; r < 4; r++) {
            const int j = w + r * 16;
            const float4 wv = ((const float4*)(w2 + j * H1))[lane];
            const float bias = b2[j];
            #pragma unroll
            for (int bb = 0; bb < BPB; bb++) {
                const float4 av = ((const float4*)a1[bb])[lane];
                float s = fmaf(av.x, wv.x, fmaf(av.y, wv.y,
                          fmaf(av.z, wv.z, av.w * wv.w)));
                s += __shfl_xor_sync(0xFFFFFFFF, s, 1);
                s += __shfl_xor_sync(0xFFFFFFFF, s, 2);
                s += __shfl_xor_sync(0xFFFFFFFF, s, 4);
                s += __shfl_xor_sync(0xFFFFFFFF, s, 8);
                s += __shfl_xor_sync(0xFFFFFFFF, s, 16);
                if (lane == 0) a2[bb][j] = fmaxf(s + bias, 0.f);
            }
        }
    }
    __syncthreads();

    // ---- Layer 3: 64 -> 3. 24 tasks, thread-per-(batch, output). ----------
    if (t < BPB * OUT) {
        const int bb = t / OUT;
        const int j = t - bb * OUT;
        const float* __restrict__ wp = w3 + j * H2;       // tiny, L1-resident
        const float* av = a2[bb];
        float s0 = b3[j], s1 = 0.f, s2 = 0.f, s3 = 0.f;
        #pragma unroll
        for (int k = 0; k < H2; k += 4) {
            s0 = fmaf(av[k + 0], wp[k + 0], s0);
            s1 = fmaf(av[k + 1], wp[k + 1], s1);
            s2 = fmaf(av[k + 2], wp[k + 2], s2);
            s3 = fmaf(av[k + 3], wp[k + 3], s3);
        }
        out[(base_b + bb) * OUT + j] = (s0 + s1) + (s2 + s3);
    }
}

extern "C" void kernel_launch(void* const* d_in, const int* in_sizes, int n_in,
                              void* d_out, int out_size) {
    const float* x     = (const float*)d_in[0];
    const float* w_ext = (const float*)d_in[1];
    const float* b_ext = (const float*)d_in[2];
    const float* w0    = (const float*)d_in[3];
    const float* b0    = (const float*)d_in[4];
    const float* w1    = (const float*)d_in[5];
    const float* b1    = (const float*)d_in[6];
    const float* w2    = (const float*)d_in[7];
    const float* b2    = (const float*)d_in[8];
    const float* w3    = (const float*)d_in[9];
    const float* b3    = (const float*)d_in[10];
    float* out = (float*)d_out;

    mean_sum_kernel<<<B_SZ * CHUNKS, 256>>>(x, w_ext, w0, w1, w2);
    mlp_kernel<<<MLP_BLOCKS, NT_MLP>>>(w_ext, b_ext, w0, b0, w1, b1,
                                       w2, b2, w3, b3, out);
}

// round 13
// speedup vs baseline: 1.2653x; 1.2653x over previous
#include <cuda_runtime.h>
#include <cuda_bf16.h>

// Problem constants (match reference)
#define B_SZ       128
#define S_SZ       4096
#define TOK        64          // token_dim
#define EFF        60          // token_dim - 4
#define NF         20          // num features
#define H0         256
#define H1         128
#define H2         64
#define OUT        3
#define CHUNKS     4
#define CHUNK_S    (S_SZ / CHUNKS)   // 1024 tokens per chunk
#define NT_MLP     512

// Scratch: partial column sums per (batch, chunk): [B, CHUNKS, TOK]
__device__ float g_partial[B_SZ * CHUNKS * TOK];

__device__ __forceinline__ void l2_prefetch(const void* p) {
    asm volatile("prefetch.global.L2 [%0];" :: "l"(p));
}

// ---------------------------------------------------------------------------
// Kernel 1: streaming column-sum (512 blocks x 256 threads — measured
// ~6.8 TB/s). Weight prefetch AFTER the streaming loop so the lines survive
// the L2 turnover caused by the 134 MB stream.
// ---------------------------------------------------------------------------
__global__ __launch_bounds__(256, 8)
void mean_sum_kernel(const float* __restrict__ x,
                     const float* __restrict__ w_ext,
                     const float* __restrict__ w0,
                     const float* __restrict__ w1,
                     const float* __restrict__ w2) {
    const int b = blockIdx.x >> 2;        // batch
    const int c = blockIdx.x & 3;         // chunk
    const int t = threadIdx.x;            // 0..255
    const int blk = blockIdx.x;           // 0..511

    const float4* __restrict__ p =
        (const float4*)(x + ((size_t)b * S_SZ + (size_t)c * CHUNK_S) * TOK);

    // 16384 float4 per block; 64 per thread.
    float4 acc = make_float4(0.f, 0.f, 0.f, 0.f);
    #pragma unroll 16
    for (int i = t; i < CHUNK_S * (TOK / 4); i += 256) {
        float4 v = __ldcs(&p[i]);         // streaming: x touched once
        acc.x += v.x; acc.y += v.y; acc.z += v.z; acc.w += v.w;
    }

    // Post-stream L2 prefetch of MLP weights (disjoint slices across blocks).
    if (t == 0)       l2_prefetch(w1 + (blk * 2 + 0) * 32);
    else if (t == 1)  l2_prefetch(w1 + (blk * 2 + 1) * 32);
    else if (t == 2 && blk < 256) l2_prefetch(w2 + blk * 32);
    else if (t == 3 && blk < 160) l2_prefetch(w0 + blk * 32);
    else if (t == 4 && blk < 38)  l2_prefetch(w_ext + blk * 32);

    __shared__ float4 sm[256];
    sm[t] = acc;
    __syncthreads();

    if (t < 16) {
        float4 s = make_float4(0.f, 0.f, 0.f, 0.f);
        #pragma unroll
        for (int k = 0; k < 16; k++) {
            float4 v = sm[t + k * 16];
            s.x += v.x; s.y += v.y; s.z += v.z; s.w += v.w;
        }
        float* dst = &g_partial[(size_t)(b * CHUNKS + c) * TOK + t * 4];
        dst[0] = s.x; dst[1] = s.y; dst[2] = s.z; dst[3] = s.w;
    }
}

// ---------------------------------------------------------------------------
// Kernel 2: per-batch MLP (128 blocks x 512 threads). All w1/w2 rows and
// biases are register-prefetched at kernel entry as one independent load
// burst (overlaps the g_partial read), so layers 1-2 run from registers.
// Per-round shfl reductions are batched so independent chains interleave.
// ---------------------------------------------------------------------------
__global__ __launch_bounds__(NT_MLP, 1)
void mlp_kernel(const float* __restrict__ w_ext, const float* __restrict__ b_ext,
                const float* __restrict__ w0, const float* __restrict__ b0,
                const float* __restrict__ w1, const float* __restrict__ b1,
                const float* __restrict__ w2, const float* __restrict__ b2,
                const float* __restrict__ w3, const float* __restrict__ b3,
                float* __restrict__ out) {
    const int b = blockIdx.x;
    const int t = threadIdx.x;
    const int w = t >> 5;                 // warp 0..15
    const int lane = t & 31;

    __shared__ float xm[TOK];
    __shared__ float feats[NF];
    __shared__ float a0[H0];
    __shared__ float a1[H1];
    __shared__ float a2[H2];

    // ---- Front-issued independent load burst (all L2-warm) ----------------
    // w1 rows for this warp's 8 neurons (j = w + 16r): 64 regs.
    float4 w1a[8], w1b[8];
    #pragma unroll
    for (int r = 0; r < 8; r++) {
        const float4* wr = (const float4*)(w1 + (w + r * 16) * H0);
        w1a[r] = wr[lane];
        w1b[r] = wr[lane + 32];
    }
    // w2 rows for this warp's 4 neurons: 16 regs.
    float4 w2v[4];
    #pragma unroll
    for (int r = 0; r < 4; r++)
        w2v[r] = ((const float4*)(w2 + (w + r * 16) * H1))[lane];
    // Biases for this warp's neurons: 12 regs.
    float bias1[8], bias2[4];
    #pragma unroll
    for (int r = 0; r < 8; r++) bias1[r] = b1[w + r * 16];
    #pragma unroll
    for (int r = 0; r < 4; r++) bias2[r] = b2[w + r * 16];

    // g_partial combine -> mean (independent of the weight burst).
    if (t < TOK) {
        const float* p0 = &g_partial[(size_t)(b * CHUNKS) * TOK + t];
        float s = (p0[0] + p0[TOK]) + (p0[2 * TOK] + p0[3 * TOK]);
        xm[t] = s * (1.0f / (float)S_SZ);
    }
    __syncthreads();

    // ---- Extractor: 20 neurons, 60-dot. Warp w does neuron w (and 16+w) ---
    {
        #pragma unroll
        for (int r = 0; r < 2; r++) {
            const int j = w + r * 16;
            if (j < NF) {
                float s = 0.f;
                if (lane < 15) {
                    const float4 wv = ((const float4*)(w_ext + j * EFF))[lane];
                    const float4 av = ((const float4*)xm)[lane];
                    s = fmaf(av.x, wv.x, fmaf(av.y, wv.y,
                        fmaf(av.z, wv.z, av.w * wv.w)));
                }
                s += __shfl_xor_sync(0xFFFFFFFF, s, 1);
                s += __shfl_xor_sync(0xFFFFFFFF, s, 2);
                s += __shfl_xor_sync(0xFFFFFFFF, s, 4);
                s += __shfl_xor_sync(0xFFFFFFFF, s, 8);
                s += __shfl_xor_sync(0xFFFFFFFF, s, 16);
                if (lane == 0) feats[j] = s + b_ext[j];
            }
        }
    }
    __syncthreads();

    // ---- Layer 0: 20 -> 256 + ReLU. One neuron per thread (t < 256). ------
    if (t < H0) {
        const float* __restrict__ wp = w0 + t * NF;
        float s0 = b0[t], s1 = 0.f;
        #pragma unroll
        for (int k = 0; k < NF; k += 2) {
            s0 = fmaf(feats[k + 0], wp[k + 0], s0);
            s1 = fmaf(feats[k + 1], wp[k + 1], s1);
        }
        a0[t] = fmaxf(s0 + s1, 0.f);
    }
    __syncthreads();

    // ---- Layer 1: 256 -> 128 + ReLU. Weights in regs; 8 partials first,
    //      then interleaved (independent) shfl-reduction chains. ------------
    {
        const float4* ar = (const float4*)a0;
        const float4 a0v = ar[lane];
        const float4 a1v = ar[lane + 32];
        float s[8];
        #pragma unroll
        for (int r = 0; r < 8; r++) {
            float p0 = fmaf(a0v.x, w1a[r].x, a0v.y * w1a[r].y);
            float p1 = fmaf(a0v.z, w1a[r].z, a0v.w * w1a[r].w);
            float p2 = fmaf(a1v.x, w1b[r].x, a1v.y * w1b[r].y);
            float p3 = fmaf(a1v.z, w1b[r].z, a1v.w * w1b[r].w);
            s[r] = (p0 + p1) + (p2 + p3);
        }
        #pragma unroll
        for (int d = 1; d <= 16; d <<= 1) {
            #pragma unroll
            for (int r = 0; r < 8; r++)
                s[r] += __shfl_xor_sync(0xFFFFFFFF, s[r], d);
        }
        if (lane == 0) {
            #pragma unroll
            for (int r = 0; r < 8; r++)
                a1[w + r * 16] = fmaxf(s[r] + bias1[r], 0.f);
        }
    }
    __syncthreads();

    // ---- Layer 2: 128 -> 64 + ReLU. Weights in regs; interleaved reduce. --
    {
        const float4 av = ((const float4*)a1)[lane];
        float s[4];
        #pragma unroll
        for (int r = 0; r < 4; r++) {
            float p0 = fmaf(av.x, w2v[r].x, av.y * w2v[r].y);
            float p1 = fmaf(av.z, w2v[r].z, av.w * w2v[r].w);
            s[r] = p0 + p1;
        }
        #pragma unroll
        for (int d = 1; d <= 16; d <<= 1) {
            #pragma unroll
            for (int r = 0; r < 4; r++)
                s[r] += __shfl_xor_sync(0xFFFFFFFF, s[r], d);
        }
        if (lane == 0) {
            #pragma unroll
            for (int r = 0; r < 4; r++)
                a2[w + r * 16] = fmaxf(s[r] + bias2[r], 0.f);
        }
    }
    __syncthreads();

    // ---- Layer 3: 64 -> 3. Warps 0..2, one neuron each. -------------------
    if (w < OUT) {
        float s = 0.f;
        if (lane < 16) {
            const float4 wv = ((const float4*)(w3 + w * H2))[lane];
            const float4 av = ((const float4*)a2)[lane];
            s = fmaf(av.x, wv.x, fmaf(av.y, wv.y,
                fmaf(av.z, wv.z, av.w * wv.w)));
        }
        s += __shfl_xor_sync(0xFFFFFFFF, s, 1);
        s += __shfl_xor_sync(0xFFFFFFFF, s, 2);
        s += __shfl_xor_sync(0xFFFFFFFF, s, 4);
        s += __shfl_xor_sync(0xFFFFFFFF, s, 8);
        s += __shfl_xor_sync(0xFFFFFFFF, s, 16);
        if (lane == 0) out[b * OUT + w] = s + b3[w];
    }
}

extern "C" void kernel_launch(void* const* d_in, const int* in_sizes, int n_in,
                              void* d_out, int out_size) {
    const float* x     = (const float*)d_in[0];
    const float* w_ext = (const float*)d_in[1];
    const float* b_ext = (const float*)d_in[2];
    const float* w0    = (const float*)d_in[3];
    const float* b0    = (const float*)d_in[4];
    const float* w1    = (const float*)d_in[5];
    const float* b1    = (const float*)d_in[6];
    const float* w2    = (const float*)d_in[7];
    const float* b2    = (const float*)d_in[8];
    const float* w3    = (const float*)d_in[9];
    const float* b3    = (const float*)d_in[10];
    float* out = (float*)d_out;

    mean_sum_kernel<<<B_SZ * CHUNKS, 256>>>(x, w_ext, w0, w1, w2);
    mlp_kernel<<<B_SZ, NT_MLP>>>(w_ext, b_ext, w0, b0, w1, b1,
                                 w2, b2, w3, b3, out);
}